// round 1
// baseline (speedup 1.0000x reference)
#include <cuda_runtime.h>
#include <cuda_bf16.h>
#include <math.h>

// Problem constants
#define VOCAB  50257
#define KCTX   8
#define EMBED  64
#define HIDDEN 1024
#define BATCH  256
#define KE     (KCTX * EMBED)   // 512

// Scratch (allocation-free rule: __device__ globals)
__device__ float g_x0[BATCH * KE];       // embedded, [256, 512]
__device__ float g_h1[BATCH * HIDDEN];   // after layer 1, [256, 1024]
__device__ float g_h2[BATCH * HIDDEN];   // after layer 2, [256, 1024]

// ---------------------------------------------------------------------------
// Kernel 1: one-hot scan + embedding gather.
// One block per (b,k) row of context (2048 blocks). Scan 50257 floats to find
// the single nonzero, then write embed_w[idx,:]*val into x0[b, k*64 .. +64].
// ---------------------------------------------------------------------------
__global__ void embed_kernel(const float* __restrict__ ctx,
                             const float* __restrict__ embed_w,
                             float* __restrict__ x0)
{
    __shared__ int   s_idx;
    __shared__ float s_val;
    if (threadIdx.x == 0) { s_idx = 0; s_val = 0.0f; }
    __syncthreads();

    const float* row = ctx + (size_t)blockIdx.x * VOCAB;
    #pragma unroll 4
    for (int v = threadIdx.x; v < VOCAB; v += blockDim.x) {
        float c = row[v];
        if (c != 0.0f) { s_idx = v; s_val = c; }   // exactly one hit -> no race
    }
    __syncthreads();

    if (threadIdx.x < EMBED) {
        float e = embed_w[(size_t)s_idx * EMBED + threadIdx.x] * s_val;
        x0[(size_t)blockIdx.x * EMBED + threadIdx.x] = e;
    }
}

// ---------------------------------------------------------------------------
// Generic tiled fp32 SGEMM: C[M,N] = act(A[M,K] @ B[K,N] + bias)
// 256 threads, (BM/TM)x(BN/TN) = 16x16 thread grid, each thread TMxTN outputs.
// Constraint: BM*BK == 1024 and BK*BN == 1024 (one element set per pass loop).
// ---------------------------------------------------------------------------
template<int BM, int BN, int BK, int TM, int TN, bool SILU>
__global__ void __launch_bounds__(256)
sgemm_kernel(const float* __restrict__ A, const float* __restrict__ B,
             const float* __restrict__ bias, float* __restrict__ C,
             int M, int N, int Kd)
{
    const int tid = threadIdx.x;
    const int tx  = tid % (BN / TN);
    const int ty  = tid / (BN / TN);
    const int block_row = blockIdx.y * BM;
    const int block_col = blockIdx.x * BN;

    __shared__ float As[BK][BM + 1];   // +1 pad: conflict-free transposed stores
    __shared__ float Bs[BK][BN];

    float acc[TM][TN];
    #pragma unroll
    for (int i = 0; i < TM; i++)
        #pragma unroll
        for (int j = 0; j < TN; j++) acc[i][j] = 0.0f;

    for (int k0 = 0; k0 < Kd; k0 += BK) {
        // Load A tile (BM x BK), store transposed As[k][m]
        #pragma unroll
        for (int e = tid; e < BM * BK; e += 256) {
            int r = e / BK, c = e % BK;
            As[c][r] = A[(size_t)(block_row + r) * Kd + k0 + c];
        }
        // Load B tile (BK x BN), guard N boundary
        #pragma unroll
        for (int e = tid; e < BK * BN; e += 256) {
            int r = e / BN, c = e % BN;
            int n = block_col + c;
            Bs[r][c] = (n < N) ? B[(size_t)(k0 + r) * N + n] : 0.0f;
        }
        __syncthreads();

        #pragma unroll
        for (int kk = 0; kk < BK; kk++) {
            float a_frag[TM], b_frag[TN];
            #pragma unroll
            for (int i = 0; i < TM; i++) a_frag[i] = As[kk][ty * TM + i];
            #pragma unroll
            for (int j = 0; j < TN; j++) b_frag[j] = Bs[kk][tx * TN + j];
            #pragma unroll
            for (int i = 0; i < TM; i++)
                #pragma unroll
                for (int j = 0; j < TN; j++)
                    acc[i][j] += a_frag[i] * b_frag[j];
        }
        __syncthreads();
    }

    // Epilogue: bias + optional silu
    #pragma unroll
    for (int i = 0; i < TM; i++) {
        int m = block_row + ty * TM + i;
        if (m >= M) continue;
        #pragma unroll
        for (int j = 0; j < TN; j++) {
            int n = block_col + tx * TN + j;
            if (n < N) {
                float v = acc[i][j] + bias[n];
                if (SILU) v = v / (1.0f + expf(-v));
                C[(size_t)m * N + n] = v;
            }
        }
    }
}

// ---------------------------------------------------------------------------
extern "C" void kernel_launch(void* const* d_in, const int* in_sizes, int n_in,
                              void* d_out, int out_size)
{
    const float* ctx     = (const float*)d_in[0];   // [256, 8*50257]
    const float* embed_w = (const float*)d_in[1];   // [50257, 64]
    const float* W1      = (const float*)d_in[2];   // [512, 1024]
    const float* b1      = (const float*)d_in[3];   // [1024]
    const float* W2      = (const float*)d_in[4];   // [1024, 1024]
    const float* b2      = (const float*)d_in[5];   // [1024]
    const float* W3      = (const float*)d_in[6];   // [1024, 50257]
    const float* b3      = (const float*)d_in[7];   // [50257]
    float*       out     = (float*)d_out;           // [256, 50257]

    float *x0, *h1, *h2;
    cudaGetSymbolAddress((void**)&x0, g_x0);
    cudaGetSymbolAddress((void**)&h1, g_h1);
    cudaGetSymbolAddress((void**)&h2, g_h2);

    // 1) embedding gather
    embed_kernel<<<BATCH * KCTX, 256>>>(ctx, embed_w, x0);

    // 2) layer 1: [256,512]@[512,1024] + b1, silu  -> 64x64 tiles, grid (16,4)
    {
        dim3 grid(HIDDEN / 64, BATCH / 64);
        sgemm_kernel<64, 64, 16, 4, 4, true><<<grid, 256>>>(
            x0, W1, b1, h1, BATCH, HIDDEN, KE);
    }

    // 3) layer 2: [256,1024]@[1024,1024] + b2, silu -> grid (16,4)
    {
        dim3 grid(HIDDEN / 64, BATCH / 64);
        sgemm_kernel<64, 64, 16, 4, 4, true><<<grid, 256>>>(
            h1, W2, b2, h2, BATCH, HIDDEN, HIDDEN);
    }

    // 4) layer 3: [256,1024]@[1024,50257] + b3 -> 128x128 tiles, grid (393,2)
    {
        dim3 grid((VOCAB + 127) / 128, BATCH / 128);
        sgemm_kernel<128, 128, 8, 8, 8, false><<<grid, 256>>>(
            h2, W3, b3, out, BATCH, VOCAB, HIDDEN);
    }
}

// round 3
// speedup vs baseline: 2.6217x; 2.6217x over previous
#include <cuda_runtime.h>
#include <cuda_fp16.h>
#include <math.h>
#include <stdint.h>

// Problem constants
#define VOCAB   50257
#define KCTX    8
#define EMBED   64
#define HIDDEN  1024
#define BATCH   256
#define KE      (KCTX * EMBED)   // 512

// ---------------------------------------------------------------------------
__device__ __forceinline__ uint32_t smem_u32_of(const void* p) {
    uint32_t a;
    asm("{ .reg .u64 t; cvta.to.shared.u64 t, %1; cvt.u32.u64 %0, t; }" : "=r"(a) : "l"(p));
    return a;
}
__device__ __forceinline__ void cp_async16(uint32_t dst, const void* src) {
    asm volatile("cp.async.ca.shared.global [%0], [%1], 16;" :: "r"(dst), "l"(src) : "memory");
}
#define CP_COMMIT() asm volatile("cp.async.commit_group;" ::: "memory")
#define CP_WAIT0()  asm volatile("cp.async.wait_group 0;" ::: "memory")

__device__ __forceinline__ void mma16816(float* d, const uint32_t* a, const uint32_t* b) {
    asm volatile(
        "mma.sync.aligned.m16n8k16.row.col.f32.f16.f16.f32 "
        "{%0,%1,%2,%3}, {%4,%5,%6,%7}, {%8,%9}, {%0,%1,%2,%3};"
        : "+f"(d[0]), "+f"(d[1]), "+f"(d[2]), "+f"(d[3])
        : "r"(a[0]), "r"(a[1]), "r"(a[2]), "r"(a[3]), "r"(b[0]), "r"(b[1]));
}

// ---------------------------------------------------------------------------
// Scratch
// ---------------------------------------------------------------------------
__device__ float  g_x0[BATCH * KE];
__device__ float  g_h1[BATCH * HIDDEN];
__device__ float  g_h2[BATCH * HIDDEN];
__device__ __half g_Ah[BATCH * HIDDEN];
__device__ __half g_Al[BATCH * HIDDEN];

// ---------------------------------------------------------------------------
// Kernel 1: one-hot scan + embedding gather (float4 vectorized)
// ---------------------------------------------------------------------------
__global__ void embed_kernel(const float* __restrict__ ctx,
                             const float* __restrict__ embed_w,
                             float* __restrict__ x0)
{
    __shared__ int   s_idx;
    __shared__ float s_val;
    if (threadIdx.x == 0) { s_idx = 0; s_val = 0.0f; }
    __syncthreads();

    size_t off = (size_t)blockIdx.x * VOCAB;
    const float* row = ctx + off;
    int a0 = (int)((4 - (off & 3)) & 3);

    for (int v = threadIdx.x; v < a0; v += blockDim.x) {
        float c = row[v];
        if (c != 0.0f) { s_idx = v; s_val = c; }
    }
    int nv4 = (VOCAB - a0) >> 2;
    const float4* row4 = (const float4*)(row + a0);
    for (int v = threadIdx.x; v < nv4; v += blockDim.x) {
        float4 c = row4[v];
        if (c.x != 0.0f || c.y != 0.0f || c.z != 0.0f || c.w != 0.0f) {
            int base = a0 + 4 * v;
            if (c.x != 0.0f) { s_idx = base;     s_val = c.x; }
            if (c.y != 0.0f) { s_idx = base + 1; s_val = c.y; }
            if (c.z != 0.0f) { s_idx = base + 2; s_val = c.z; }
            if (c.w != 0.0f) { s_idx = base + 3; s_val = c.w; }
        }
    }
    for (int v = a0 + 4 * nv4 + threadIdx.x; v < VOCAB; v += blockDim.x) {
        float c = row[v];
        if (c != 0.0f) { s_idx = v; s_val = c; }
    }
    __syncthreads();

    if (threadIdx.x < EMBED) {
        float e = embed_w[(size_t)s_idx * EMBED + threadIdx.x] * s_val;
        x0[(size_t)blockIdx.x * EMBED + threadIdx.x] = e;
    }
}

// ---------------------------------------------------------------------------
// fp32 SGEMM for the two small layers (exact)
// ---------------------------------------------------------------------------
template<int BM, int BN, int BK, int TM, int TN, bool SILU>
__global__ void __launch_bounds__(256)
sgemm_kernel(const float* __restrict__ A, const float* __restrict__ B,
             const float* __restrict__ bias, float* __restrict__ C,
             int M, int N, int Kd)
{
    const int tid = threadIdx.x;
    const int tx  = tid % (BN / TN);
    const int ty  = tid / (BN / TN);
    const int block_row = blockIdx.y * BM;
    const int block_col = blockIdx.x * BN;

    __shared__ float As[BK][BM + 1];
    __shared__ float Bs[BK][BN];

    float acc[TM][TN];
    #pragma unroll
    for (int i = 0; i < TM; i++)
        #pragma unroll
        for (int j = 0; j < TN; j++) acc[i][j] = 0.0f;

    for (int k0 = 0; k0 < Kd; k0 += BK) {
        #pragma unroll
        for (int e = tid; e < BM * BK; e += 256) {
            int r = e / BK, c = e % BK;
            As[c][r] = A[(size_t)(block_row + r) * Kd + k0 + c];
        }
        #pragma unroll
        for (int e = tid; e < BK * BN; e += 256) {
            int r = e / BN, c = e % BN;
            Bs[r][c] = B[(size_t)(k0 + r) * N + block_col + c];
        }
        __syncthreads();

        #pragma unroll
        for (int kk = 0; kk < BK; kk++) {
            float a_frag[TM], b_frag[TN];
            #pragma unroll
            for (int i = 0; i < TM; i++) a_frag[i] = As[kk][ty * TM + i];
            #pragma unroll
            for (int j = 0; j < TN; j++) b_frag[j] = Bs[kk][tx * TN + j];
            #pragma unroll
            for (int i = 0; i < TM; i++)
                #pragma unroll
                for (int j = 0; j < TN; j++)
                    acc[i][j] += a_frag[i] * b_frag[j];
        }
        __syncthreads();
    }

    #pragma unroll
    for (int i = 0; i < TM; i++) {
        int m = block_row + ty * TM + i;
        #pragma unroll
        for (int j = 0; j < TN; j++) {
            int n = block_col + tx * TN + j;
            float v = acc[i][j] + bias[n];
            if (SILU) v = v / (1.0f + expf(-v));
            C[(size_t)m * N + n] = v;
        }
    }
}

// ---------------------------------------------------------------------------
// Split h2 (fp32) -> fp16 hi/lo planes (A error ~2^-22)
// ---------------------------------------------------------------------------
__global__ void convertA_kernel(const float* __restrict__ h2,
                                __half* __restrict__ Ah,
                                __half* __restrict__ Al)
{
    int i = blockIdx.x * blockDim.x + threadIdx.x;
    if (i < BATCH * HIDDEN) {
        float x = h2[i];
        __half h = __float2half_rn(x);
        Ah[i] = h;
        Al[i] = __float2half_rn(x - __half2float(h));
    }
}

// ---------------------------------------------------------------------------
// GEMM3: out[256, VOCAB] = h2 @ W3 + b3 via mma.sync (HMMA), 2-pass fp16.
// One CTA: M=256 (all batch) x N=128 tile, K=1024 in 32 chunks of 32.
// A planes (fp16 hi/lo) via cp.async; W3 fp32 read once, converted to fp16.
// ---------------------------------------------------------------------------
#define KC       32
#define NC       (HIDDEN / KC)     // 32
#define A_ROWF16 40                 // 32 data + 8 pad (80B rows, bank-clean)
#define A_PLANE  (256 * A_ROWF16 * 2)        // 20480 B
#define B_ROWB   272                // 128 f16 + pad (17 x 16B)
#define B_BYTES  (KC * B_ROWB)      // 8704 B
#define BUF_B    (2 * A_PLANE + B_BYTES)     // 49664 B
#define SMEM_G3  (2 * BUF_B)                 // 99328 B

__global__ void __launch_bounds__(256)
gemm3_kernel(const __half* __restrict__ Ah, const __half* __restrict__ Al,
             const float* __restrict__ W3, const float* __restrict__ bias,
             float* __restrict__ out)
{
    extern __shared__ __align__(16) char smem[];
    const uint32_t smb = smem_u32_of(smem);
    const int tid  = threadIdx.x;
    const int lane = tid & 31;
    const int wid  = tid >> 5;
    const int n0   = blockIdx.x * 128;
    const int wm0  = (wid >> 1) * 64;   // 4 warps along M
    const int wn0  = (wid & 1) * 64;    // 2 warps along N

    float acc[4][8][4];
    #pragma unroll
    for (int i = 0; i < 4; i++)
        #pragma unroll
        for (int j = 0; j < 8; j++)
            #pragma unroll
            for (int q = 0; q < 4; q++) acc[i][j][q] = 0.0f;

    // staging ids
    const int a_row = tid >> 2, a_seg = tid & 3;   // A: 16B pieces
    const int b_row = tid >> 3, b_t7  = tid & 7;   // B: rows of 32, pair-strided

    // ldmatrix per-lane base byte offsets (within a buffer)
    const uint32_t a_lm = (uint32_t)((wm0 + (lane & 15)) * 80 + (lane >> 4) * 16);
    const uint32_t b_lm = (uint32_t)((lane & 15) * B_ROWB + (wn0 + (lane >> 4) * 8) * 2);

    float vB[16];

    auto stageA = [&](int c, uint32_t bufb) {
        #pragma unroll
        for (int q = 0; q < 4; q++) {
            int row = a_row + 64 * q;
            uint32_t d = bufb + (uint32_t)(row * 80 + a_seg * 16);
            const __half* s0 = Ah + (size_t)row * HIDDEN + c * KC + a_seg * 8;
            const __half* s1 = Al + (size_t)row * HIDDEN + c * KC + a_seg * 8;
            cp_async16(d, s0);
            cp_async16(d + A_PLANE, s1);
        }
    };
    auto ldgB = [&](int c) {
        const float* src = W3 + (size_t)(c * KC + b_row) * VOCAB;
        #pragma unroll
        for (int i = 0; i < 8; i++) {
            int n1 = n0 + 16 * i + 2 * b_t7;
            vB[2 * i]     = (n1     < VOCAB) ? __ldg(src + n1)     : 0.0f;
            vB[2 * i + 1] = (n1 + 1 < VOCAB) ? __ldg(src + n1 + 1) : 0.0f;
        }
    };
    auto stsB = [&](uint32_t bufb) {
        #pragma unroll
        for (int i = 0; i < 8; i++) {
            __half2 h = __floats2half2_rn(vB[2 * i], vB[2 * i + 1]);
            uint32_t d = bufb + 2 * A_PLANE
                       + (uint32_t)(b_row * B_ROWB + (16 * i + 2 * b_t7) * 2);
            asm volatile("st.shared.b32 [%0], %1;" :: "r"(d), "r"(*(uint32_t*)&h) : "memory");
        }
    };
    auto compute = [&](uint32_t bufb) {
        #pragma unroll
        for (int ks = 0; ks < 2; ks++) {
            uint32_t bf[8][2];
            #pragma unroll
            for (int j = 0; j < 4; j++) {
                uint32_t addr = bufb + 2 * A_PLANE + b_lm + ks * 16 * B_ROWB + j * 32;
                asm volatile(
                    "ldmatrix.sync.aligned.m8n8.x4.trans.shared.b16 {%0,%1,%2,%3}, [%4];"
                    : "=r"(bf[2*j][0]), "=r"(bf[2*j][1]), "=r"(bf[2*j+1][0]), "=r"(bf[2*j+1][1])
                    : "r"(addr));
            }
            #pragma unroll
            for (int pl = 0; pl < 2; pl++) {
                uint32_t af[4][4];
                #pragma unroll
                for (int i = 0; i < 4; i++) {
                    uint32_t addr = bufb + pl * A_PLANE + a_lm + i * 16 * 80 + ks * 32;
                    asm volatile(
                        "ldmatrix.sync.aligned.m8n8.x4.shared.b16 {%0,%1,%2,%3}, [%4];"
                        : "=r"(af[i][0]), "=r"(af[i][1]), "=r"(af[i][2]), "=r"(af[i][3])
                        : "r"(addr));
                }
                #pragma unroll
                for (int i = 0; i < 4; i++)
                    #pragma unroll
                    for (int j = 0; j < 8; j++)
                        mma16816(acc[i][j], af[i], bf[j]);
            }
        }
    };

    // --- prologue: chunk 0 ---
    stageA(0, smb); CP_COMMIT();
    ldgB(0);
    CP_WAIT0();
    stsB(smb);
    __syncthreads();

    // --- mainloop ---
    for (int c = 0; c < NC; c++) {
        const uint32_t bufc = smb + (uint32_t)(c & 1) * BUF_B;
        const uint32_t bufn = smb + (uint32_t)((c + 1) & 1) * BUF_B;
        if (c + 1 < NC) { ldgB(c + 1); stageA(c + 1, bufn); CP_COMMIT(); }
        compute(bufc);
        if (c + 1 < NC) {
            CP_WAIT0();
            __syncthreads();
            stsB(bufn);
            __syncthreads();
        }
    }

    // --- epilogue: bias + guarded stores ---
    #pragma unroll
    for (int i = 0; i < 4; i++) {
        int m = wm0 + 16 * i + (lane >> 2);
        #pragma unroll
        for (int j = 0; j < 8; j++) {
            int n = n0 + wn0 + 8 * j + (lane & 3) * 2;
            if (n + 1 < VOCAB) {
                float b0 = __ldg(bias + n), b1 = __ldg(bias + n + 1);
                out[(size_t)m * VOCAB + n]           = acc[i][j][0] + b0;
                out[(size_t)m * VOCAB + n + 1]       = acc[i][j][1] + b1;
                out[(size_t)(m + 8) * VOCAB + n]     = acc[i][j][2] + b0;
                out[(size_t)(m + 8) * VOCAB + n + 1] = acc[i][j][3] + b1;
            } else if (n < VOCAB) {
                float b0 = __ldg(bias + n);
                out[(size_t)m * VOCAB + n]       = acc[i][j][0] + b0;
                out[(size_t)(m + 8) * VOCAB + n] = acc[i][j][2] + b0;
            }
        }
    }
}

// ---------------------------------------------------------------------------
extern "C" void kernel_launch(void* const* d_in, const int* in_sizes, int n_in,
                              void* d_out, int out_size)
{
    const float* ctx     = (const float*)d_in[0];
    const float* embed_w = (const float*)d_in[1];
    const float* W1      = (const float*)d_in[2];
    const float* b1      = (const float*)d_in[3];
    const float* W2      = (const float*)d_in[4];
    const float* b2      = (const float*)d_in[5];
    const float* W3      = (const float*)d_in[6];
    const float* b3      = (const float*)d_in[7];
    float*       out     = (float*)d_out;

    float *x0, *h1, *h2;
    __half *ah, *al;
    cudaGetSymbolAddress((void**)&x0, g_x0);
    cudaGetSymbolAddress((void**)&h1, g_h1);
    cudaGetSymbolAddress((void**)&h2, g_h2);
    cudaGetSymbolAddress((void**)&ah, g_Ah);
    cudaGetSymbolAddress((void**)&al, g_Al);

    cudaFuncSetAttribute(gemm3_kernel,
                         cudaFuncAttributeMaxDynamicSharedMemorySize, SMEM_G3);

    embed_kernel<<<BATCH * KCTX, 256>>>(ctx, embed_w, x0);

    {
        dim3 grid(HIDDEN / 64, BATCH / 64);
        sgemm_kernel<64, 64, 16, 4, 4, true><<<grid, 256>>>(x0, W1, b1, h1, BATCH, HIDDEN, KE);
    }
    {
        dim3 grid(HIDDEN / 64, BATCH / 64);
        sgemm_kernel<64, 64, 16, 4, 4, true><<<grid, 256>>>(h1, W2, b2, h2, BATCH, HIDDEN, HIDDEN);
    }

    convertA_kernel<<<(BATCH * HIDDEN + 255) / 256, 256>>>(h2, ah, al);

    gemm3_kernel<<<(VOCAB + 127) / 128, 256, SMEM_G3>>>(ah, al, W3, b3, out);
}

// round 4
// speedup vs baseline: 3.3110x; 1.2629x over previous
#include <cuda_runtime.h>
#include <cuda_fp16.h>
#include <math.h>
#include <stdint.h>

// Problem constants
#define VOCAB   50257
#define KCTX    8
#define EMBED   64
#define HIDDEN  1024
#define BATCH   256
#define KE      (KCTX * EMBED)   // 512

// ---------------------------------------------------------------------------
__device__ __forceinline__ uint32_t smem_u32_of(const void* p) {
    uint32_t a;
    asm("{ .reg .u64 t; cvta.to.shared.u64 t, %1; cvt.u32.u64 %0, t; }" : "=r"(a) : "l"(p));
    return a;
}
__device__ __forceinline__ void cp_async16(uint32_t dst, const void* src) {
    asm volatile("cp.async.ca.shared.global [%0], [%1], 16;" :: "r"(dst), "l"(src) : "memory");
}
#define CP_COMMIT() asm volatile("cp.async.commit_group;" ::: "memory")
#define CP_WAIT0()  asm volatile("cp.async.wait_group 0;" ::: "memory")

__device__ __forceinline__ void mma16816(float* d, const uint32_t* a, const uint32_t* b) {
    asm volatile(
        "mma.sync.aligned.m16n8k16.row.col.f32.f16.f16.f32 "
        "{%0,%1,%2,%3}, {%4,%5,%6,%7}, {%8,%9}, {%0,%1,%2,%3};"
        : "+f"(d[0]), "+f"(d[1]), "+f"(d[2]), "+f"(d[3])
        : "r"(a[0]), "r"(a[1]), "r"(a[2]), "r"(a[3]), "r"(b[0]), "r"(b[1]));
}

// ---------------------------------------------------------------------------
// Scratch
// ---------------------------------------------------------------------------
__device__ float  g_x0[BATCH * KE];
__device__ float  g_h1[BATCH * HIDDEN];
__device__ __half g_Ah[BATCH * HIDDEN];

// ---------------------------------------------------------------------------
// Kernel 1: one-hot scan + embedding gather (float4 vectorized)
// ---------------------------------------------------------------------------
__global__ void embed_kernel(const float* __restrict__ ctx,
                             const float* __restrict__ embed_w,
                             float* __restrict__ x0)
{
    __shared__ int   s_idx;
    __shared__ float s_val;
    if (threadIdx.x == 0) { s_idx = 0; s_val = 0.0f; }
    __syncthreads();

    size_t off = (size_t)blockIdx.x * VOCAB;
    const float* row = ctx + off;
    int a0 = (int)((4 - (off & 3)) & 3);

    for (int v = threadIdx.x; v < a0; v += blockDim.x) {
        float c = row[v];
        if (c != 0.0f) { s_idx = v; s_val = c; }
    }
    int nv4 = (VOCAB - a0) >> 2;
    const float4* row4 = (const float4*)(row + a0);
    for (int v = threadIdx.x; v < nv4; v += blockDim.x) {
        float4 c = row4[v];
        if (c.x != 0.0f || c.y != 0.0f || c.z != 0.0f || c.w != 0.0f) {
            int base = a0 + 4 * v;
            if (c.x != 0.0f) { s_idx = base;     s_val = c.x; }
            if (c.y != 0.0f) { s_idx = base + 1; s_val = c.y; }
            if (c.z != 0.0f) { s_idx = base + 2; s_val = c.z; }
            if (c.w != 0.0f) { s_idx = base + 3; s_val = c.w; }
        }
    }
    for (int v = a0 + 4 * nv4 + threadIdx.x; v < VOCAB; v += blockDim.x) {
        float c = row[v];
        if (c != 0.0f) { s_idx = v; s_val = c; }
    }
    __syncthreads();

    if (threadIdx.x < EMBED) {
        float e = embed_w[(size_t)s_idx * EMBED + threadIdx.x] * s_val;
        x0[(size_t)blockIdx.x * EMBED + threadIdx.x] = e;
    }
}

// ---------------------------------------------------------------------------
// fp32 SGEMM for the two small layers (exact); TO = output type (fp32 or fp16)
// ---------------------------------------------------------------------------
template<int BM, int BN, int BK, int TM, int TN, bool SILU, typename TO>
__global__ void __launch_bounds__(256)
sgemm_kernel(const float* __restrict__ A, const float* __restrict__ B,
             const float* __restrict__ bias, TO* __restrict__ C,
             int M, int N, int Kd)
{
    const int tid = threadIdx.x;
    const int tx  = tid % (BN / TN);
    const int ty  = tid / (BN / TN);
    const int block_row = blockIdx.y * BM;
    const int block_col = blockIdx.x * BN;

    __shared__ float As[BK][BM + 1];
    __shared__ float Bs[BK][BN];

    float acc[TM][TN];
    #pragma unroll
    for (int i = 0; i < TM; i++)
        #pragma unroll
        for (int j = 0; j < TN; j++) acc[i][j] = 0.0f;

    for (int k0 = 0; k0 < Kd; k0 += BK) {
        #pragma unroll
        for (int e = tid; e < BM * BK; e += 256) {
            int r = e / BK, c = e % BK;
            As[c][r] = A[(size_t)(block_row + r) * Kd + k0 + c];
        }
        #pragma unroll
        for (int e = tid; e < BK * BN; e += 256) {
            int r = e / BN, c = e % BN;
            Bs[r][c] = B[(size_t)(k0 + r) * N + block_col + c];
        }
        __syncthreads();

        #pragma unroll
        for (int kk = 0; kk < BK; kk++) {
            float a_frag[TM], b_frag[TN];
            #pragma unroll
            for (int i = 0; i < TM; i++) a_frag[i] = As[kk][ty * TM + i];
            #pragma unroll
            for (int j = 0; j < TN; j++) b_frag[j] = Bs[kk][tx * TN + j];
            #pragma unroll
            for (int i = 0; i < TM; i++)
                #pragma unroll
                for (int j = 0; j < TN; j++)
                    acc[i][j] += a_frag[i] * b_frag[j];
        }
        __syncthreads();
    }

    #pragma unroll
    for (int i = 0; i < TM; i++) {
        int m = block_row + ty * TM + i;
        #pragma unroll
        for (int j = 0; j < TN; j++) {
            int n = block_col + tx * TN + j;
            float v = acc[i][j] + bias[n];
            if (SILU) v = v / (1.0f + expf(-v));
            if constexpr (sizeof(TO) == 2)
                C[(size_t)m * N + n] = __float2half_rn(v);
            else
                C[(size_t)m * N + n] = v;
        }
    }
}

// ---------------------------------------------------------------------------
// GEMM3: out[256, VOCAB] = h2 @ W3 + b3 via mma.sync (HMMA), single-pass fp16.
// One CTA: M=256 (all batch) x N=128 tile, K=1024 in 32 chunks of 32.
// A (fp16, written by layer-2 epilogue) via cp.async; W3 fp32 read once,
// coalesced scalar LDG -> fp16 -> smem. One __syncthreads per chunk.
// ---------------------------------------------------------------------------
#define KC       32
#define NC       (HIDDEN / KC)            // 32
#define A_ROWB   80                        // 32 f16 (64B) + 16B pad
#define A_BYTES  (256 * A_ROWB)            // 20480
#define B_ROWB   272                       // 128 f16 (256B) + 16B pad
#define B_BYTES  (KC * B_ROWB)             // 8704
#define OFF_B    A_BYTES
#define BUF_B    (A_BYTES + B_BYTES)       // 29184
#define SMEM_G3  (2 * BUF_B)               // 58368

__global__ void __launch_bounds__(256)
gemm3_kernel(const __half* __restrict__ Ah,
             const float* __restrict__ W3, const float* __restrict__ bias,
             float* __restrict__ out)
{
    extern __shared__ __align__(16) char smem[];
    const uint32_t smb = smem_u32_of(smem);
    const int tid  = threadIdx.x;
    const int lane = tid & 31;
    const int wid  = tid >> 5;
    const int n0   = blockIdx.x * 128;
    const int wm0  = (wid >> 1) * 64;   // 4 warps along M
    const int wn0  = (wid & 1) * 64;    // 2 warps along N

    float acc[4][8][4];
    #pragma unroll
    for (int i = 0; i < 4; i++)
        #pragma unroll
        for (int j = 0; j < 8; j++)
            #pragma unroll
            for (int q = 0; q < 4; q++) acc[i][j][q] = 0.0f;

    // A staging ids: 16B pieces, 256 rows x 4 segs
    const int a_row = tid >> 2, a_seg = tid & 3;

    // ldmatrix per-lane base byte offsets (within a buffer)
    const uint32_t a_lm = (uint32_t)((wm0 + (lane & 15)) * A_ROWB + (lane >> 4) * 16);
    const uint32_t b_lm = (uint32_t)((lane & 15) * B_ROWB + (wn0 + (lane >> 4) * 8) * 2);

    float vB[16];   // B chunk fragment: 4 rows x 4 col-groups per thread

    auto stageA = [&](int c, uint32_t bufb) {
        #pragma unroll
        for (int q = 0; q < 4; q++) {
            int row = a_row + 64 * q;
            uint32_t d = bufb + (uint32_t)(row * A_ROWB + a_seg * 16);
            cp_async16(d, Ah + (size_t)row * HIDDEN + c * KC + a_seg * 8);
        }
    };
    // fully coalesced: warp 'wid' covers row (wid + 8*rr); lane+32*e cols
    auto ldgB = [&](int c) {
        #pragma unroll
        for (int rr = 0; rr < 4; rr++) {
            const float* src = W3 + (size_t)(c * KC + wid + 8 * rr) * VOCAB;
            #pragma unroll
            for (int e = 0; e < 4; e++) {
                int n = n0 + lane + 32 * e;
                vB[rr * 4 + e] = (n < VOCAB) ? __ldg(src + n) : 0.0f;
            }
        }
    };
    auto stsB = [&](uint32_t bufb) {
        #pragma unroll
        for (int rr = 0; rr < 4; rr++) {
            #pragma unroll
            for (int e = 0; e < 4; e++) {
                __half h = __float2half_rn(vB[rr * 4 + e]);
                uint32_t d = bufb + OFF_B
                           + (uint32_t)((wid + 8 * rr) * B_ROWB + (lane + 32 * e) * 2);
                asm volatile("st.shared.u16 [%0], %1;"
                             :: "r"(d), "h"(*(uint16_t*)&h) : "memory");
            }
        }
    };
    auto compute = [&](uint32_t bufb) {
        #pragma unroll
        for (int ks = 0; ks < 2; ks++) {
            uint32_t bf[8][2];
            #pragma unroll
            for (int j = 0; j < 4; j++) {
                uint32_t addr = bufb + OFF_B + b_lm + ks * 16 * B_ROWB + j * 32;
                asm volatile(
                    "ldmatrix.sync.aligned.m8n8.x4.trans.shared.b16 {%0,%1,%2,%3}, [%4];"
                    : "=r"(bf[2*j][0]), "=r"(bf[2*j][1]), "=r"(bf[2*j+1][0]), "=r"(bf[2*j+1][1])
                    : "r"(addr));
            }
            uint32_t af[4][4];
            #pragma unroll
            for (int i = 0; i < 4; i++) {
                uint32_t addr = bufb + a_lm + i * 16 * A_ROWB + ks * 32;
                asm volatile(
                    "ldmatrix.sync.aligned.m8n8.x4.shared.b16 {%0,%1,%2,%3}, [%4];"
                    : "=r"(af[i][0]), "=r"(af[i][1]), "=r"(af[i][2]), "=r"(af[i][3])
                    : "r"(addr));
            }
            #pragma unroll
            for (int i = 0; i < 4; i++)
                #pragma unroll
                for (int j = 0; j < 8; j++)
                    mma16816(acc[i][j], af[i], bf[j]);
        }
    };

    // --- prologue: chunk 0 ---
    stageA(0, smb); CP_COMMIT();
    ldgB(0);
    CP_WAIT0();
    stsB(smb);
    __syncthreads();

    // --- mainloop: one barrier per chunk; B LDGs issued before compute ---
    for (int c = 0; c < NC; c++) {
        const uint32_t bufc = smb + (uint32_t)(c & 1) * BUF_B;
        const uint32_t bufn = smb + (uint32_t)((c + 1) & 1) * BUF_B;
        if (c + 1 < NC) { ldgB(c + 1); stageA(c + 1, bufn); CP_COMMIT(); }
        compute(bufc);
        if (c + 1 < NC) {
            stsB(bufn);       // bufn free since end of chunk c-1
            CP_WAIT0();
            __syncthreads();
        }
    }

    // --- epilogue: bias + guarded stores ---
    #pragma unroll
    for (int i = 0; i < 4; i++) {
        int m = wm0 + 16 * i + (lane >> 2);
        #pragma unroll
        for (int j = 0; j < 8; j++) {
            int n = n0 + wn0 + 8 * j + (lane & 3) * 2;
            if (n + 1 < VOCAB) {
                float b0 = __ldg(bias + n), b1 = __ldg(bias + n + 1);
                out[(size_t)m * VOCAB + n]           = acc[i][j][0] + b0;
                out[(size_t)m * VOCAB + n + 1]       = acc[i][j][1] + b1;
                out[(size_t)(m + 8) * VOCAB + n]     = acc[i][j][2] + b0;
                out[(size_t)(m + 8) * VOCAB + n + 1] = acc[i][j][3] + b1;
            } else if (n < VOCAB) {
                float b0 = __ldg(bias + n);
                out[(size_t)m * VOCAB + n]       = acc[i][j][0] + b0;
                out[(size_t)(m + 8) * VOCAB + n] = acc[i][j][2] + b0;
            }
        }
    }
}

// ---------------------------------------------------------------------------
extern "C" void kernel_launch(void* const* d_in, const int* in_sizes, int n_in,
                              void* d_out, int out_size)
{
    const float* ctx     = (const float*)d_in[0];
    const float* embed_w = (const float*)d_in[1];
    const float* W1      = (const float*)d_in[2];
    const float* b1      = (const float*)d_in[3];
    const float* W2      = (const float*)d_in[4];
    const float* b2      = (const float*)d_in[5];
    const float* W3      = (const float*)d_in[6];
    const float* b3      = (const float*)d_in[7];
    float*       out     = (float*)d_out;

    float *x0, *h1;
    __half *ah;
    cudaGetSymbolAddress((void**)&x0, g_x0);
    cudaGetSymbolAddress((void**)&h1, g_h1);
    cudaGetSymbolAddress((void**)&ah, g_Ah);

    cudaFuncSetAttribute(gemm3_kernel,
                         cudaFuncAttributeMaxDynamicSharedMemorySize, SMEM_G3);

    embed_kernel<<<BATCH * KCTX, 256>>>(ctx, embed_w, x0);

    {
        dim3 grid(HIDDEN / 64, BATCH / 64);
        sgemm_kernel<64, 64, 16, 4, 4, true, float><<<grid, 256>>>(
            x0, W1, b1, h1, BATCH, HIDDEN, KE);
    }
    {   // layer 2 writes fp16 activations directly (GEMM3's A operand)
        dim3 grid(HIDDEN / 64, BATCH / 64);
        sgemm_kernel<64, 64, 16, 4, 4, true, __half><<<grid, 256>>>(
            h1, W2, b2, ah, BATCH, HIDDEN, HIDDEN);
    }

    gemm3_kernel<<<(VOCAB + 127) / 128, 256, SMEM_G3>>>(ah, W3, b3, out);
}